// round 8
// baseline (speedup 1.0000x reference)
#include <cuda_runtime.h>
#include <math.h>

#define B_   8192
#define F_   32
#define V_   64
#define C_   32
#define K_   8
#define KP_  7
#define FM1  31
#define EPS_ 1e-6f
#define VC_  (V_ * C_)          // 2048
#define VVC_ (V_ * V_ * C_)     // 131072
#define NFK  (FM1 * KP_)        // 217

#define NPREP  (32 + NFK * 8)   // 1768 prep-role blocks
#define NPAIRS (B_ / 2)         // 4096 pairs-role blocks (2 elements each)
#define NINTER (3 * NPREP)      // 5304: pattern [pairs,pairs,prep]
#define NGRID  (NINTER + (NPAIRS - 2 * NPREP))   // 5864

// Scratch (no cudaMalloc allowed)
__device__ float g_T[F_ * VC_];             // fused gather table = 256KB
__device__ float g_sexp[NFK * 4 * VC_];     // pair exp-sum partials = 7.1MB
__device__ float g_psum[B_ * C_];           // per-element pair partial sums = 1MB

// ---------------------------------------------------------------------------
// Gate-row helper: gumbel-softmax weights for structure row i (0..30).
// ---------------------------------------------------------------------------
__device__ __forceinline__ void gate_row(int i, const float* __restrict__ sl,
                                         const float* __restrict__ un,
                                         float* __restrict__ wout) {
    int nv = 1 + ((i + 1 < KP_) ? (i + 1) : KP_);
    float gate[K_];
    float m = -1e30f;
#pragma unroll
    for (int k = 0; k < K_; k++) {
        if (k < nv) {
            float u = un[i * K_ + k];
            float g = -logf(-logf(u + EPS_) + EPS_);
            gate[k] = sl[i * K_ + k] + g;
            m = fmaxf(m, gate[k]);
        }
    }
    float s = 0.f;
#pragma unroll
    for (int k = 0; k < K_; k++)
        if (k < nv) { gate[k] = expf(gate[k] - m); s += gate[k]; }
    float inv = 1.f / s;
#pragma unroll
    for (int k = 0; k < K_; k++)
        wout[k] = (k < nv) ? gate[k] * inv : 0.f;
}

// ---------------------------------------------------------------------------
// Fused kernel, register-lean: indices live in smem, 4 warps per element.
//   bid < NINTER : bid%3==2 -> prep(bid/3), else pairs(2*(bid/3)+bid%3)
//   bid >= NINTER: pairs(2*NPREP + bid - NINTER)
// ---------------------------------------------------------------------------
__global__ void __launch_bounds__(256, 6) k_fused(const int* __restrict__ x,
                                                  const float* __restrict__ cls,
                                                  const float* __restrict__ t0,
                                                  const float* __restrict__ st,
                                                  const float* __restrict__ pt,
                                                  const float* __restrict__ sl,
                                                  const float* __restrict__ un) {
    int bid = blockIdx.x;
    int tid = threadIdx.x;
    int role, ridx;
    if (bid < NINTER) {
        int g = bid / 3, r = bid - g * 3;
        if (r == 2) { role = 0; ridx = g; }
        else        { role = 1; ridx = 2 * g + r; }
    } else { role = 1; ridx = 2 * NPREP + (bid - NINTER); }

    if (role == 1) {
        // =================== pairs role: 2 elements, 4 warps each ==========
        __shared__ float s_w[FM1 * K_];
        __shared__ int   s_x[2][F_];
        __shared__ float s_part[8][C_];
        if (tid < FM1) gate_row(tid, sl, un, &s_w[tid * K_]);
        if (tid < 2 * F_) s_x[tid >> 5][tid & 31] = x[(ridx * 2) * F_ + tid];
        __syncthreads();

        int warp = tid >> 5;
        int lane = tid & 31;
        int h    = warp & 3;             // quarter 0..3
        int e    = warp >> 2;            // element 0..1
        const int* xr = s_x[e];

        float a0 = 0.f, a1 = 0.f;

        if (h == 0) {
            // i = 0..9 : 49 gathers (nk = min(i+1,7))
#pragma unroll
            for (int i = 0; i < 10; i++) {
                int xs = xr[i + 1];
                int base = i * KP_ * VVC_ + xs * VC_ + lane;
                const int nk = (i + 1 < KP_) ? (i + 1) : KP_;
#pragma unroll
                for (int k = 0; k < nk; k++) {
                    int off   = base + k * VVC_ + xr[i - k] * C_;
                    float val = __ldg(&pt[off]);
                    float w   = s_w[i * K_ + k + 1];
                    if (k & 1) a1 = fmaf(w, val, a1); else a0 = fmaf(w, val, a0);
                }
            }
        } else {
            // i = ibase..ibase+6, all nk = 7 : 49 gathers (one code path)
            int ibase = 3 + 7 * h;       // 10, 17, 24
#pragma unroll
            for (int d = 0; d < 7; d++) {
                int i  = ibase + d;
                int xs = xr[i + 1];
                int base = i * (KP_ * VVC_) + xs * VC_ + lane;
#pragma unroll
                for (int k = 0; k < KP_; k++) {
                    int off   = base + k * VVC_ + xr[i - k] * C_;
                    float val = __ldg(&pt[off]);
                    float w   = s_w[i * K_ + k + 1];
                    if (k & 1) a1 = fmaf(w, val, a1); else a0 = fmaf(w, val, a0);
                }
            }
        }

        s_part[warp][lane] = a0 + a1;
        __syncthreads();
        if (h == 0) {
            int b = ridx * 2 + e;
            g_psum[b * C_ + lane] = s_part[warp][lane] + s_part[warp + 1][lane]
                                  + s_part[warp + 2][lane] + s_part[warp + 3][lane];
        }
        return;
    }

    // =================== prep role ===================
    if (ridx >= 32) {
        int q    = ridx - 32;            // 0..1735
        int fk   = q >> 3;               // 0..216
        int part = q & 1;
        int vq   = (q >> 1) & 3;
        const float4* base = (const float4*)(pt + (size_t)fk * VVC_)
                             + vq * 16 * (VC_ / 4);
        int t = part * 256 + tid;
        float s0 = 0.f, s1 = 0.f, s2 = 0.f, s3 = 0.f;
#pragma unroll
        for (int v = 0; v < 16; v++) {
            float4 r = __ldg(base + v * (VC_ / 4) + t);
            s0 += __expf(r.x); s1 += __expf(r.y);
            s2 += __expf(r.z); s3 += __expf(r.w);
        }
        float4 o; o.x = s0; o.y = s1; o.z = s2; o.w = s3;
        ((float4*)(g_sexp + (fk * 4 + vq) * VC_))[t] = o;
        return;
    }

    __shared__ float s_lse[C_];
    __shared__ float s_scalar;
    int j = ridx;

    if (j == 0) {
        if (tid == 0) {
            float m = -1e30f;
            for (int c = 0; c < C_; c++) m = fmaxf(m, cls[c]);
            float s = 0.f;
            for (int c = 0; c < C_; c++) s += expf(cls[c] - m);
            s_scalar = m + logf(s);
        }
        if (tid < C_) {
            float m = -1e30f;
            for (int v = 0; v < V_; v++) m = fmaxf(m, t0[v * C_ + tid]);
            float s = 0.f;
            for (int v = 0; v < V_; v++) s += expf(t0[v * C_ + tid] - m);
            s_lse[tid] = m + logf(s);
        }
        __syncthreads();
        for (int p = tid; p < VC_; p += blockDim.x) {
            int c = p & (C_ - 1);
            g_T[p] = (cls[c] - s_scalar) + (t0[p] - s_lse[c]);
        }
    } else {
        int f = j - 1;
        const float* stf = st + f * VC_;
        if (tid == 0) {
            float w[K_];
            gate_row(f, sl, un, w);
            s_scalar = w[0];
        }
        if (tid < C_) {
            float m = -1e30f;
            for (int v = 0; v < V_; v++) m = fmaxf(m, stf[v * C_ + tid]);
            float s = 0.f;
            for (int v = 0; v < V_; v++) s += expf(stf[v * C_ + tid] - m);
            s_lse[tid] = m + logf(s);
        }
        __syncthreads();
        float w0 = s_scalar;
        for (int p = tid; p < VC_; p += blockDim.x) {
            int c = p & (C_ - 1);
            g_T[j * VC_ + p] = w0 * (stf[p] - s_lse[c]);
        }
    }
}

// ---------------------------------------------------------------------------
// Kernel 2: fold weighted pair-LSE corrections into T (sum 4 partials + log).
// ---------------------------------------------------------------------------
__global__ void __launch_bounds__(1024) k_fold(const float* __restrict__ sl,
                                               const float* __restrict__ un) {
    __shared__ float s_w[FM1 * K_];
    if (threadIdx.x < FM1) gate_row(threadIdx.x, sl, un, &s_w[threadIdx.x * K_]);
    __syncthreads();

    int e = blockIdx.x * 1024 + threadIdx.x;
    int m = e >> 11;
    int p = e & (VC_ - 1);
    int jmax = (6 < 30 - m) ? 6 : (30 - m);
    float acc = 0.f;
#pragma unroll
    for (int jj = 0; jj < KP_; jj++) {
        if (jj <= jmax) {
            int i  = m + jj;
            int fk = i * KP_ + jj;
            float s = __ldg(&g_sexp[(fk * 4 + 0) * VC_ + p])
                    + __ldg(&g_sexp[(fk * 4 + 1) * VC_ + p])
                    + __ldg(&g_sexp[(fk * 4 + 2) * VC_ + p])
                    + __ldg(&g_sexp[(fk * 4 + 3) * VC_ + p]);
            acc = fmaf(s_w[i * K_ + jj + 1], __logf(s), acc);
        }
    }
    g_T[m * VC_ + p] -= acc;
}

// ---------------------------------------------------------------------------
// Kernel 3: T gathers + add pair partials. Two warps per element.
// ---------------------------------------------------------------------------
__global__ void __launch_bounds__(256) k_mainT(const int* __restrict__ x,
                                               float* __restrict__ out) {
    __shared__ float s_part[8][C_];
    int warp = threadIdx.x >> 5;
    int lane = threadIdx.x & 31;
    int half = warp & 1;
    int b    = blockIdx.x * 4 + (warp >> 1);

    const int4* xr = (const int4*)(x + b * F_) + half * 4;
    int xv[16];
#pragma unroll
    for (int q = 0; q < 4; q++) {
        int4 v = __ldg(&xr[q]);
        xv[4 * q + 0] = v.x; xv[4 * q + 1] = v.y;
        xv[4 * q + 2] = v.z; xv[4 * q + 3] = v.w;
    }
    int jbase = half * 16;
    float a0 = 0.f, a1 = 0.f;
#pragma unroll
    for (int j = 0; j < 16; j++) {
        float t = __ldg(&g_T[((jbase + j) * V_ + xv[j]) * C_ + lane]);
        if (j & 1) a1 += t; else a0 += t;
    }
    float r = a0 + a1;
    s_part[warp][lane] = r;
    __syncthreads();
    if (half == 0)
        out[b * C_ + lane] = r + s_part[warp + 1][lane] + g_psum[b * C_ + lane];
}

// ---------------------------------------------------------------------------
extern "C" void kernel_launch(void* const* d_in, const int* in_sizes, int n_in,
                              void* d_out, int out_size) {
    const int* x = (const int*)d_in[0];
    int idx = 1;
    if (in_sizes[1] == 1) idx = 2;   // skip scalar 'training' if present
    const float* cls = (const float*)d_in[idx++];
    const float* t0  = (const float*)d_in[idx++];
    const float* st  = (const float*)d_in[idx++];
    const float* pt  = (const float*)d_in[idx++];
    const float* sl  = (const float*)d_in[idx++];
    const float* un  = (const float*)d_in[idx++];
    float* out = (float*)d_out;

    k_fused<<<NGRID, 256>>>(x, cls, t0, st, pt, sl, un);
    k_fold<<<62, 1024>>>(sl, un);
    k_mainT<<<B_ / 4, 256>>>(x, out);
}

// round 11
// speedup vs baseline: 1.2822x; 1.2822x over previous
#include <cuda_runtime.h>
#include <math.h>

#define B_   8192
#define F_   32
#define V_   64
#define C_   32
#define K_   8
#define KP_  7
#define FM1  31
#define EPS_ 1e-6f
#define VC_  (V_ * C_)          // 2048
#define VVC_ (V_ * V_ * C_)     // 131072
#define NFK  (FM1 * KP_)        // 217

#define NPREP  (32 + NFK * 8)   // 1768 prep-role blocks
#define NPAIRS (B_ / 4)         // 2048 pairs-role blocks (4 elements each)
#define NINTER (2 * NPREP)      // 3536 interleaved region
#define NGRID  (NINTER + (NPAIRS - NPREP))   // 3816

// Scratch (no cudaMalloc allowed)
__device__ float g_T[F_ * VC_];             // fused gather table = 256KB
__device__ float g_sexp[NFK * 4 * VC_];     // pair exp-sum partials = 7.1MB
__device__ float g_psum[B_ * C_];           // per-element pair partial sums = 1MB

// ---------------------------------------------------------------------------
// Compile-time (i,k) enumeration for gather n within feature range [i0,i1).
// __host__ __device__ so they are legal in device constexpr contexts.
// ---------------------------------------------------------------------------
__host__ __device__ constexpr int IMIN_(int a, int b) { return a < b ? a : b; }
__host__ __device__ constexpr int gi_of(int n, int i0, int i1) {
    for (int i = i0; i < i1; i++) {
        int nk = IMIN_(i + 1, KP_);
        if (n < nk) return i;
        n -= nk;
    }
    return 0;
}
__host__ __device__ constexpr int gk_of(int n, int i0, int i1) {
    for (int i = i0; i < i1; i++) {
        int nk = IMIN_(i + 1, KP_);
        if (n < nk) return n;
        n -= nk;
    }
    return 0;
}

// Recursive template loop: iteration T handles paired gathers 2T and 2T+1.
// All (i,k) are constexpr -> xv[] indexing is compile-time -> registers.
template<int T, int NT, int I0, int I1, int BOFF>
struct PairLoop {
    static __device__ __forceinline__ void run(const int* __restrict__ xv,
                                               const float* __restrict__ s_w,
                                               const float* __restrict__ pt,
                                               int hw, int lc,
                                               float& a0, float& a1) {
        constexpr int iA = gi_of(2 * T,     I0, I1);
        constexpr int kA = gk_of(2 * T,     I0, I1);
        constexpr int iB = gi_of(2 * T + 1, I0, I1);
        constexpr int kB = gk_of(2 * T + 1, I0, I1);
        int offA = (iA * KP_ + kA) * VVC_ + xv[iA + 1 - BOFF] * VC_ + xv[iA - kA - BOFF] * C_;
        int offB = (iB * KP_ + kB) * VVC_ + xv[iB + 1 - BOFF] * VC_ + xv[iB - kB - BOFF] * C_;
        int off  = hw ? offB : offA;
        float w  = s_w[hw ? (iB * K_ + kB + 1) : (iA * K_ + kA + 1)];
        float2 v = __ldg((const float2*)(pt + off) + lc);
        a0 = fmaf(w, v.x, a0);
        a1 = fmaf(w, v.y, a1);
        PairLoop<T + 1, NT, I0, I1, BOFF>::run(xv, s_w, pt, hw, lc, a0, a1);
    }
};
template<int NT, int I0, int I1, int BOFF>
struct PairLoop<NT, NT, I0, I1, BOFF> {
    static __device__ __forceinline__ void run(const int*, const float*,
                                               const float*, int, int,
                                               float&, float&) {}
};

// ---------------------------------------------------------------------------
// Gate-row helper: gumbel-softmax weights for structure row i (0..30).
// ---------------------------------------------------------------------------
__device__ __forceinline__ void gate_row(int i, const float* __restrict__ sl,
                                         const float* __restrict__ un,
                                         float* __restrict__ wout) {
    int nv = 1 + ((i + 1 < KP_) ? (i + 1) : KP_);
    float gate[K_];
    float m = -1e30f;
#pragma unroll
    for (int k = 0; k < K_; k++) {
        if (k < nv) {
            float u = un[i * K_ + k];
            float g = -logf(-logf(u + EPS_) + EPS_);
            gate[k] = sl[i * K_ + k] + g;
            m = fmaxf(m, gate[k]);
        }
    }
    float s = 0.f;
#pragma unroll
    for (int k = 0; k < K_; k++)
        if (k < nv) { gate[k] = expf(gate[k] - m); s += gate[k]; }
    float inv = 1.f / s;
#pragma unroll
    for (int k = 0; k < K_; k++)
        wout[k] = (k < nv) ? gate[k] * inv : 0.f;
}

// ---------------------------------------------------------------------------
// Fused kernel: interleaved roles (even bid -> prep, odd -> pairs in the
// first NINTER blocks). Pairs role: 4 elements/block, 2 warps/element,
// 49 paired LDG.64 gathers per warp, indices register-resident.
// ---------------------------------------------------------------------------
__global__ void __launch_bounds__(256) k_fused(const int* __restrict__ x,
                                               const float* __restrict__ cls,
                                               const float* __restrict__ t0,
                                               const float* __restrict__ st,
                                               const float* __restrict__ pt,
                                               const float* __restrict__ sl,
                                               const float* __restrict__ un) {
    int bid = blockIdx.x;
    int tid = threadIdx.x;
    int role, ridx;
    if (bid < NINTER) { role = bid & 1; ridx = bid >> 1; }
    else              { role = 1;       ridx = NPREP + (bid - NINTER); }

    if (role == 1) {
        // =================== pairs role ===================
        __shared__ float  s_w[FM1 * K_];
        __shared__ float2 s_p2[8][16];
        if (tid < FM1) gate_row(tid, sl, un, &s_w[tid * K_]);
        __syncthreads();

        int warp = tid >> 5;
        int lane = tid & 31;
        int half = warp & 1;
        int hw   = lane >> 4;            // which gather of the pair
        int lc   = lane & 15;            // c-pair index (c = 2*lc, 2*lc+1)
        int b    = ridx * 4 + (warp >> 1);

        const int4* xr = (const int4*)(x + b * F_);
        float a0 = 0.f, a1 = 0.f;

        if (half == 0) {
            // i = 0..16 : 98 gathers = 49 pairs; needs x[0..17]
            int xv[20];
#pragma unroll
            for (int q = 0; q < 5; q++) {
                int4 v = __ldg(&xr[q]);
                xv[4 * q + 0] = v.x; xv[4 * q + 1] = v.y;
                xv[4 * q + 2] = v.z; xv[4 * q + 3] = v.w;
            }
            PairLoop<0, 49, 0, 17, 0>::run(xv, s_w, pt, hw, lc, a0, a1);
        } else {
            // i = 17..30 : 98 gathers = 49 pairs; needs x[11..31], base 8
            int xv[24];
#pragma unroll
            for (int q = 2; q < 8; q++) {
                int4 v = __ldg(&xr[q]);
                xv[4 * q - 8] = v.x; xv[4 * q - 7] = v.y;
                xv[4 * q - 6] = v.z; xv[4 * q - 5] = v.w;
            }
            PairLoop<0, 49, 17, 31, 8>::run(xv, s_w, pt, hw, lc, a0, a1);
        }

        // Combine even/odd gather halves within the warp.
        a0 += __shfl_down_sync(0xffffffffu, a0, 16);
        a1 += __shfl_down_sync(0xffffffffu, a1, 16);
        if (hw == 0) s_p2[warp][lc] = make_float2(a0, a1);
        __syncthreads();
        if (half == 0 && hw == 0) {
            float2 m = s_p2[warp][lc];
            float2 o = s_p2[warp + 1][lc];
            ((float2*)(g_psum + b * C_))[lc] = make_float2(m.x + o.x, m.y + o.y);
        }
        return;
    }

    // =================== prep role ===================
    if (ridx >= 32) {
        int q    = ridx - 32;            // 0..1735
        int fk   = q >> 3;               // 0..216
        int part = q & 1;
        int vq   = (q >> 1) & 3;
        const float4* base = (const float4*)(pt + (size_t)fk * VVC_)
                             + vq * 16 * (VC_ / 4);
        int t = part * 256 + tid;
        float s0 = 0.f, s1 = 0.f, s2 = 0.f, s3 = 0.f;
#pragma unroll
        for (int v = 0; v < 16; v++) {
            float4 r = __ldg(base + v * (VC_ / 4) + t);
            s0 += __expf(r.x); s1 += __expf(r.y);
            s2 += __expf(r.z); s3 += __expf(r.w);
        }
        float4 o; o.x = s0; o.y = s1; o.z = s2; o.w = s3;
        ((float4*)(g_sexp + (fk * 4 + vq) * VC_))[t] = o;
        return;
    }

    __shared__ float s_lse[C_];
    __shared__ float s_scalar;
    int j = ridx;

    if (j == 0) {
        if (tid == 0) {
            float m = -1e30f;
            for (int c = 0; c < C_; c++) m = fmaxf(m, cls[c]);
            float s = 0.f;
            for (int c = 0; c < C_; c++) s += expf(cls[c] - m);
            s_scalar = m + logf(s);
        }
        if (tid < C_) {
            float m = -1e30f;
            for (int v = 0; v < V_; v++) m = fmaxf(m, t0[v * C_ + tid]);
            float s = 0.f;
            for (int v = 0; v < V_; v++) s += expf(t0[v * C_ + tid] - m);
            s_lse[tid] = m + logf(s);
        }
        __syncthreads();
        for (int p = tid; p < VC_; p += blockDim.x) {
            int c = p & (C_ - 1);
            g_T[p] = (cls[c] - s_scalar) + (t0[p] - s_lse[c]);
        }
    } else {
        int f = j - 1;
        const float* stf = st + f * VC_;
        if (tid == 0) {
            float w[K_];
            gate_row(f, sl, un, w);
            s_scalar = w[0];
        }
        if (tid < C_) {
            float m = -1e30f;
            for (int v = 0; v < V_; v++) m = fmaxf(m, stf[v * C_ + tid]);
            float s = 0.f;
            for (int v = 0; v < V_; v++) s += expf(stf[v * C_ + tid] - m);
            s_lse[tid] = m + logf(s);
        }
        __syncthreads();
        float w0 = s_scalar;
        for (int p = tid; p < VC_; p += blockDim.x) {
            int c = p & (C_ - 1);
            g_T[j * VC_ + p] = w0 * (stf[p] - s_lse[c]);
        }
    }
}

// ---------------------------------------------------------------------------
// Kernel 2: fold weighted pair-LSE corrections into T (sum 4 partials + log).
// ---------------------------------------------------------------------------
__global__ void __launch_bounds__(1024) k_fold(const float* __restrict__ sl,
                                               const float* __restrict__ un) {
    __shared__ float s_w[FM1 * K_];
    if (threadIdx.x < FM1) gate_row(threadIdx.x, sl, un, &s_w[threadIdx.x * K_]);
    __syncthreads();

    int e = blockIdx.x * 1024 + threadIdx.x;
    int m = e >> 11;
    int p = e & (VC_ - 1);
    int jmax = (6 < 30 - m) ? 6 : (30 - m);
    float acc = 0.f;
#pragma unroll
    for (int jj = 0; jj < KP_; jj++) {
        if (jj <= jmax) {
            int i  = m + jj;
            int fk = i * KP_ + jj;
            float s = __ldg(&g_sexp[(fk * 4 + 0) * VC_ + p])
                    + __ldg(&g_sexp[(fk * 4 + 1) * VC_ + p])
                    + __ldg(&g_sexp[(fk * 4 + 2) * VC_ + p])
                    + __ldg(&g_sexp[(fk * 4 + 3) * VC_ + p]);
            acc = fmaf(s_w[i * K_ + jj + 1], __logf(s), acc);
        }
    }
    g_T[m * VC_ + p] -= acc;
}

// ---------------------------------------------------------------------------
// Kernel 3: T gathers + add pair partials. Two warps per element.
// ---------------------------------------------------------------------------
__global__ void __launch_bounds__(256) k_mainT(const int* __restrict__ x,
                                               float* __restrict__ out) {
    __shared__ float s_part[8][C_];
    int warp = threadIdx.x >> 5;
    int lane = threadIdx.x & 31;
    int half = warp & 1;
    int b    = blockIdx.x * 4 + (warp >> 1);

    const int4* xr = (const int4*)(x + b * F_) + half * 4;
    int xv[16];
#pragma unroll
    for (int q = 0; q < 4; q++) {
        int4 v = __ldg(&xr[q]);
        xv[4 * q + 0] = v.x; xv[4 * q + 1] = v.y;
        xv[4 * q + 2] = v.z; xv[4 * q + 3] = v.w;
    }
    int jbase = half * 16;
    float a0 = 0.f, a1 = 0.f;
#pragma unroll
    for (int j = 0; j < 16; j++) {
        float t = __ldg(&g_T[((jbase + j) * V_ + xv[j]) * C_ + lane]);
        if (j & 1) a1 += t; else a0 += t;
    }
    float r = a0 + a1;
    s_part[warp][lane] = r;
    __syncthreads();
    if (half == 0)
        out[b * C_ + lane] = r + s_part[warp + 1][lane] + g_psum[b * C_ + lane];
}

// ---------------------------------------------------------------------------
extern "C" void kernel_launch(void* const* d_in, const int* in_sizes, int n_in,
                              void* d_out, int out_size) {
    const int* x = (const int*)d_in[0];
    int idx = 1;
    if (in_sizes[1] == 1) idx = 2;   // skip scalar 'training' if present
    const float* cls = (const float*)d_in[idx++];
    const float* t0  = (const float*)d_in[idx++];
    const float* st  = (const float*)d_in[idx++];
    const float* pt  = (const float*)d_in[idx++];
    const float* sl  = (const float*)d_in[idx++];
    const float* un  = (const float*)d_in[idx++];
    float* out = (float*)d_out;

    k_fused<<<NGRID, 256>>>(x, cls, t0, st, pt, sl, un);
    k_fold<<<62, 1024>>>(sl, un);
    k_mainT<<<B_ / 4, 256>>>(x, out);
}

// round 12
// speedup vs baseline: 1.2888x; 1.0052x over previous
#include <cuda_runtime.h>
#include <math.h>

#define B_   8192
#define F_   32
#define V_   64
#define C_   32
#define K_   8
#define KP_  7
#define FM1  31
#define EPS_ 1e-6f
#define VC_  (V_ * C_)          // 2048
#define VVC_ (V_ * V_ * C_)     // 131072
#define NFK  (FM1 * KP_)        // 217

#define NPREP  (32 + NFK * 8)   // 1768 prep-role blocks
#define NPAIRS (B_ / 4)         // 2048 pairs-role blocks (4 elements each)
#define NINTER (2 * NPREP)      // 3536 interleaved region
#define NGRID  (NINTER + (NPAIRS - NPREP))   // 3816

// Scratch (no cudaMalloc allowed)
__device__ float g_T[F_ * VC_];             // fused gather table = 256KB
__device__ float g_sexp[NFK * 4 * VC_];     // pair exp-sum partials = 7.1MB
__device__ float g_psum[B_ * C_];           // per-element pair partial sums = 1MB

// ---------------------------------------------------------------------------
// Compile-time (i,k) enumeration over the FULL gather list (i = 0..30,
// k = 0..min(i+1,7)-1), 196 entries total.
// ---------------------------------------------------------------------------
__host__ __device__ constexpr int IMIN_(int a, int b) { return a < b ? a : b; }
__host__ __device__ constexpr int gi_of(int n) {
    for (int i = 0; i < FM1; i++) {
        int nk = IMIN_(i + 1, KP_);
        if (n < nk) return i;
        n -= nk;
    }
    return 0;
}
__host__ __device__ constexpr int gk_of(int n) {
    for (int i = 0; i < FM1; i++) {
        int nk = IMIN_(i + 1, KP_);
        if (n < nk) return n;
        n -= nk;
    }
    return 0;
}

// Recursive template loop: iteration T handles gathers N0+4T .. N0+4T+3 with
// ONE LDG.128 (quarter-warp qw selects the gather, lq selects the c-float4).
template<int T, int NT, int N0, int BOFF>
struct QuadLoop {
    static __device__ __forceinline__ void run(const int* __restrict__ xv,
                                               const float* __restrict__ s_w,
                                               const float* __restrict__ pt,
                                               int qw, int lq,
                                               float& a0, float& a1,
                                               float& a2, float& a3) {
        constexpr int iA = gi_of(N0 + 4 * T + 0), kA = gk_of(N0 + 4 * T + 0);
        constexpr int iB = gi_of(N0 + 4 * T + 1), kB = gk_of(N0 + 4 * T + 1);
        constexpr int iC = gi_of(N0 + 4 * T + 2), kC = gk_of(N0 + 4 * T + 2);
        constexpr int iD = gi_of(N0 + 4 * T + 3), kD = gk_of(N0 + 4 * T + 3);
        int offA = (iA * KP_ + kA) * VVC_ + xv[iA + 1 - BOFF] * VC_ + xv[iA - kA - BOFF] * C_;
        int offB = (iB * KP_ + kB) * VVC_ + xv[iB + 1 - BOFF] * VC_ + xv[iB - kB - BOFF] * C_;
        int offC = (iC * KP_ + kC) * VVC_ + xv[iC + 1 - BOFF] * VC_ + xv[iC - kC - BOFF] * C_;
        int offD = (iD * KP_ + kD) * VVC_ + xv[iD + 1 - BOFF] * VC_ + xv[iD - kD - BOFF] * C_;
        int offAB = (qw & 1) ? offB : offA;
        int offCD = (qw & 1) ? offD : offC;
        int off   = (qw & 2) ? offCD : offAB;
        int wAB = (qw & 1) ? (iB * K_ + kB + 1) : (iA * K_ + kA + 1);
        int wCD = (qw & 1) ? (iD * K_ + kD + 1) : (iC * K_ + kC + 1);
        float w = s_w[(qw & 2) ? wCD : wAB];
        float4 v = __ldg((const float4*)(pt + off) + lq);
        a0 = fmaf(w, v.x, a0);
        a1 = fmaf(w, v.y, a1);
        a2 = fmaf(w, v.z, a2);
        a3 = fmaf(w, v.w, a3);
        QuadLoop<T + 1, NT, N0, BOFF>::run(xv, s_w, pt, qw, lq, a0, a1, a2, a3);
    }
};
template<int NT, int N0, int BOFF>
struct QuadLoop<NT, NT, N0, BOFF> {
    static __device__ __forceinline__ void run(const int*, const float*,
                                               const float*, int, int,
                                               float&, float&, float&, float&) {}
};

// ---------------------------------------------------------------------------
// Gate-row helper: gumbel-softmax weights for structure row i (0..30).
// ---------------------------------------------------------------------------
__device__ __forceinline__ void gate_row(int i, const float* __restrict__ sl,
                                         const float* __restrict__ un,
                                         float* __restrict__ wout) {
    int nv = 1 + ((i + 1 < KP_) ? (i + 1) : KP_);
    float gate[K_];
    float m = -1e30f;
#pragma unroll
    for (int k = 0; k < K_; k++) {
        if (k < nv) {
            float u = un[i * K_ + k];
            float g = -logf(-logf(u + EPS_) + EPS_);
            gate[k] = sl[i * K_ + k] + g;
            m = fmaxf(m, gate[k]);
        }
    }
    float s = 0.f;
#pragma unroll
    for (int k = 0; k < K_; k++)
        if (k < nv) { gate[k] = expf(gate[k] - m); s += gate[k]; }
    float inv = 1.f / s;
#pragma unroll
    for (int k = 0; k < K_; k++)
        wout[k] = (k < nv) ? gate[k] * inv : 0.f;
}

// ---------------------------------------------------------------------------
// Fused kernel: interleaved roles (even bid -> prep, odd -> pairs in the
// first NINTER blocks). Pairs role: 4 elements/block, 2 warps/element,
// quad LDG.128 gathers (warp0: gathers 0..95, warp1: 96..195).
// ---------------------------------------------------------------------------
__global__ void __launch_bounds__(256) k_fused(const int* __restrict__ x,
                                               const float* __restrict__ cls,
                                               const float* __restrict__ t0,
                                               const float* __restrict__ st,
                                               const float* __restrict__ pt,
                                               const float* __restrict__ sl,
                                               const float* __restrict__ un) {
    int bid = blockIdx.x;
    int tid = threadIdx.x;
    int role, ridx;
    if (bid < NINTER) { role = bid & 1; ridx = bid >> 1; }
    else              { role = 1;       ridx = NPREP + (bid - NINTER); }

    if (role == 1) {
        // =================== pairs role ===================
        __shared__ float  s_w[FM1 * K_];
        __shared__ float4 s_p4[8][8];
        if (tid < FM1) gate_row(tid, sl, un, &s_w[tid * K_]);
        __syncthreads();

        int warp = tid >> 5;
        int lane = tid & 31;
        int half = warp & 1;
        int qw   = lane >> 3;            // which gather of the quad (0..3)
        int lq   = lane & 7;             // c-float4 index (c = 4*lq..4*lq+3)
        int b    = ridx * 4 + (warp >> 1);

        const int4* xr = (const int4*)(x + b * F_);
        float a0 = 0.f, a1 = 0.f, a2 = 0.f, a3 = 0.f;

        if (half == 0) {
            // gathers 0..95 (i = 0..16,k<=4); needs x[0..17]
            int xv[20];
#pragma unroll
            for (int q = 0; q < 5; q++) {
                int4 v = __ldg(&xr[q]);
                xv[4 * q + 0] = v.x; xv[4 * q + 1] = v.y;
                xv[4 * q + 2] = v.z; xv[4 * q + 3] = v.w;
            }
            QuadLoop<0, 24, 0, 0>::run(xv, s_w, pt, qw, lq, a0, a1, a2, a3);
        } else {
            // gathers 96..195 (i = 16 k>=5, 17..30); needs x[10..31], base 8
            int xv[24];
#pragma unroll
            for (int q = 2; q < 8; q++) {
                int4 v = __ldg(&xr[q]);
                xv[4 * q - 8] = v.x; xv[4 * q - 7] = v.y;
                xv[4 * q - 6] = v.z; xv[4 * q - 5] = v.w;
            }
            QuadLoop<0, 25, 96, 8>::run(xv, s_w, pt, qw, lq, a0, a1, a2, a3);
        }

        // Reduce across the 4 quarter-warps (same lq, different qw).
        a0 += __shfl_down_sync(0xffffffffu, a0, 16);
        a1 += __shfl_down_sync(0xffffffffu, a1, 16);
        a2 += __shfl_down_sync(0xffffffffu, a2, 16);
        a3 += __shfl_down_sync(0xffffffffu, a3, 16);
        a0 += __shfl_down_sync(0xffffffffu, a0, 8);
        a1 += __shfl_down_sync(0xffffffffu, a1, 8);
        a2 += __shfl_down_sync(0xffffffffu, a2, 8);
        a3 += __shfl_down_sync(0xffffffffu, a3, 8);
        if (qw == 0) s_p4[warp][lq] = make_float4(a0, a1, a2, a3);
        __syncthreads();
        if (half == 0 && qw == 0) {
            float4 m = s_p4[warp][lq];
            float4 o = s_p4[warp + 1][lq];
            ((float4*)(g_psum + b * C_))[lq] =
                make_float4(m.x + o.x, m.y + o.y, m.z + o.z, m.w + o.w);
        }
        return;
    }

    // =================== prep role ===================
    if (ridx >= 32) {
        int q    = ridx - 32;            // 0..1735
        int fk   = q >> 3;               // 0..216
        int part = q & 1;
        int vq   = (q >> 1) & 3;
        const float4* base = (const float4*)(pt + (size_t)fk * VVC_)
                             + vq * 16 * (VC_ / 4);
        int t = part * 256 + tid;
        float s0 = 0.f, s1 = 0.f, s2 = 0.f, s3 = 0.f;
#pragma unroll
        for (int v = 0; v < 16; v++) {
            float4 r = __ldg(base + v * (VC_ / 4) + t);
            s0 += __expf(r.x); s1 += __expf(r.y);
            s2 += __expf(r.z); s3 += __expf(r.w);
        }
        float4 o; o.x = s0; o.y = s1; o.z = s2; o.w = s3;
        ((float4*)(g_sexp + (fk * 4 + vq) * VC_))[t] = o;
        return;
    }

    __shared__ float s_lse[C_];
    __shared__ float s_scalar;
    int j = ridx;

    if (j == 0) {
        if (tid == 0) {
            float m = -1e30f;
            for (int c = 0; c < C_; c++) m = fmaxf(m, cls[c]);
            float s = 0.f;
            for (int c = 0; c < C_; c++) s += expf(cls[c] - m);
            s_scalar = m + logf(s);
        }
        if (tid < C_) {
            float m = -1e30f;
            for (int v = 0; v < V_; v++) m = fmaxf(m, t0[v * C_ + tid]);
            float s = 0.f;
            for (int v = 0; v < V_; v++) s += expf(t0[v * C_ + tid] - m);
            s_lse[tid] = m + logf(s);
        }
        __syncthreads();
        for (int p = tid; p < VC_; p += blockDim.x) {
            int c = p & (C_ - 1);
            g_T[p] = (cls[c] - s_scalar) + (t0[p] - s_lse[c]);
        }
    } else {
        int f = j - 1;
        const float* stf = st + f * VC_;
        if (tid == 0) {
            float w[K_];
            gate_row(f, sl, un, w);
            s_scalar = w[0];
        }
        if (tid < C_) {
            float m = -1e30f;
            for (int v = 0; v < V_; v++) m = fmaxf(m, stf[v * C_ + tid]);
            float s = 0.f;
            for (int v = 0; v < V_; v++) s += expf(stf[v * C_ + tid] - m);
            s_lse[tid] = m + logf(s);
        }
        __syncthreads();
        float w0 = s_scalar;
        for (int p = tid; p < VC_; p += blockDim.x) {
            int c = p & (C_ - 1);
            g_T[j * VC_ + p] = w0 * (stf[p] - s_lse[c]);
        }
    }
}

// ---------------------------------------------------------------------------
// Kernel 2: fold weighted pair-LSE corrections into T (sum 4 partials + log).
// ---------------------------------------------------------------------------
__global__ void __launch_bounds__(1024) k_fold(const float* __restrict__ sl,
                                               const float* __restrict__ un) {
    __shared__ float s_w[FM1 * K_];
    if (threadIdx.x < FM1) gate_row(threadIdx.x, sl, un, &s_w[threadIdx.x * K_]);
    __syncthreads();

    int e = blockIdx.x * 1024 + threadIdx.x;
    int m = e >> 11;
    int p = e & (VC_ - 1);
    int jmax = (6 < 30 - m) ? 6 : (30 - m);
    float acc = 0.f;
#pragma unroll
    for (int jj = 0; jj < KP_; jj++) {
        if (jj <= jmax) {
            int i  = m + jj;
            int fk = i * KP_ + jj;
            float s = __ldg(&g_sexp[(fk * 4 + 0) * VC_ + p])
                    + __ldg(&g_sexp[(fk * 4 + 1) * VC_ + p])
                    + __ldg(&g_sexp[(fk * 4 + 2) * VC_ + p])
                    + __ldg(&g_sexp[(fk * 4 + 3) * VC_ + p]);
            acc = fmaf(s_w[i * K_ + jj + 1], __logf(s), acc);
        }
    }
    g_T[m * VC_ + p] -= acc;
}

// ---------------------------------------------------------------------------
// Kernel 3: T gathers + add pair partials. Two warps per element.
// ---------------------------------------------------------------------------
__global__ void __launch_bounds__(256) k_mainT(const int* __restrict__ x,
                                               float* __restrict__ out) {
    __shared__ float s_part[8][C_];
    int warp = threadIdx.x >> 5;
    int lane = threadIdx.x & 31;
    int half = warp & 1;
    int b    = blockIdx.x * 4 + (warp >> 1);

    const int4* xr = (const int4*)(x + b * F_) + half * 4;
    int xv[16];
#pragma unroll
    for (int q = 0; q < 4; q++) {
        int4 v = __ldg(&xr[q]);
        xv[4 * q + 0] = v.x; xv[4 * q + 1] = v.y;
        xv[4 * q + 2] = v.z; xv[4 * q + 3] = v.w;
    }
    int jbase = half * 16;
    float a0 = 0.f, a1 = 0.f;
#pragma unroll
    for (int j = 0; j < 16; j++) {
        float t = __ldg(&g_T[((jbase + j) * V_ + xv[j]) * C_ + lane]);
        if (j & 1) a1 += t; else a0 += t;
    }
    float r = a0 + a1;
    s_part[warp][lane] = r;
    __syncthreads();
    if (half == 0)
        out[b * C_ + lane] = r + s_part[warp + 1][lane] + g_psum[b * C_ + lane];
}

// ---------------------------------------------------------------------------
extern "C" void kernel_launch(void* const* d_in, const int* in_sizes, int n_in,
                              void* d_out, int out_size) {
    const int* x = (const int*)d_in[0];
    int idx = 1;
    if (in_sizes[1] == 1) idx = 2;   // skip scalar 'training' if present
    const float* cls = (const float*)d_in[idx++];
    const float* t0  = (const float*)d_in[idx++];
    const float* st  = (const float*)d_in[idx++];
    const float* pt  = (const float*)d_in[idx++];
    const float* sl  = (const float*)d_in[idx++];
    const float* un  = (const float*)d_in[idx++];
    float* out = (float*)d_out;

    k_fused<<<NGRID, 256>>>(x, cls, t0, st, pt, sl, un);
    k_fold<<<62, 1024>>>(sl, un);
    k_mainT<<<B_ / 4, 256>>>(x, out);
}